// round 1
// baseline (speedup 1.0000x reference)
#include <cuda_runtime.h>
#include <cstdint>

#define BB 4
#define TT 4096
#define DD 2048
#define BOT 256

// Scratch (device globals: allocation-free rule)
__device__ float g_scores[(size_t)BB * TT * TT];      // 256 MB: scores -> combined
__device__ float g_qk[(size_t)BB * TT * 2 * BOT];     // 32 MB: q (cols 0..255) | k (256..511)
__device__ float g_w[2 * BOT * DD];                   // 4 MB packed [Wq;Wk]
__device__ float g_bias[2 * BOT];

__device__ __forceinline__ float to_tf32(float x) {
    uint32_t u;
    asm("cvt.rna.tf32.f32 %0, %1;" : "=r"(u) : "f"(x));
    return __uint_as_float(u);
}

__global__ void pack_w(const float* __restrict__ Wq, const float* __restrict__ Wk,
                       const float* __restrict__ bq, const float* __restrict__ bk) {
    for (int i = blockIdx.x * blockDim.x + threadIdx.x; i < 2 * BOT * DD;
         i += gridDim.x * blockDim.x) {
        int n = i / DD, k = i - n * DD;
        g_w[i] = (n < BOT) ? Wq[n * DD + k] : Wk[(n - BOT) * DD + k];
    }
    int j = blockIdx.x * blockDim.x + threadIdx.x;
    if (j < 2 * BOT) g_bias[j] = (j < BOT) ? bq[j] : bk[j - BOT];
}

// ---------------------------------------------------------------------------
// TF32 tiled GEMM: C[M,N] = A[M,K] * B (+epilogue). 128x128x16 tile, 256 thr.
// B_KMAJOR=true : B is [N,K], K contiguous (NT).  false: B is [K,N] (NN).
// MODE: 0 plain store, 1 add g_bias[col], 2 scores (mask j<=i-4, *scale)
// ---------------------------------------------------------------------------
template <int MODE, bool B_KMAJOR>
__global__ __launch_bounds__(256) void gemm_tf32(
    const float* __restrict__ A, const float* __restrict__ Bm, float* __restrict__ C,
    int M, int N, int K, int lda, int ldb, int ldc,
    long sA, long sB, long sC, float scale) {
    const int m0 = blockIdx.y * 128;
    const int n0 = blockIdx.x * 128;
    A += (long)blockIdx.z * sA;
    Bm += (long)blockIdx.z * sB;
    C += (long)blockIdx.z * sC;
    const int t = threadIdx.x;

    if (MODE == 2 && n0 > m0 + 123) {  // fully-masked tile: no allowed (i,j)
        const float4 f = make_float4(-65000.f, -65000.f, -65000.f, -65000.f);
        #pragma unroll
        for (int s = 0; s < 16; ++s) {
            int v = t + s * 256;
            int row = v >> 5, c4 = (v & 31) << 2;
            *(float4*)(C + (long)(m0 + row) * ldc + n0 + c4) = f;
        }
        return;
    }

    __shared__ float As[128][20];
    __shared__ float Bs[128][20];

    const int warp = t >> 5, lane = t & 31;
    const int wm = warp >> 2, wn = warp & 3;  // warps 2x4 -> 64x32 per warp
    const int g = lane >> 2, tg = lane & 3;

    float acc[4][4][4];
    #pragma unroll
    for (int i = 0; i < 4; i++)
        #pragma unroll
        for (int j = 0; j < 4; j++)
            #pragma unroll
            for (int r = 0; r < 4; r++) acc[i][j][r] = 0.f;

    for (int k0 = 0; k0 < K; k0 += 16) {
        #pragma unroll
        for (int s = 0; s < 2; ++s) {  // A tile 128x16
            int v = t + s * 256;
            int row = v >> 2, c4 = (v & 3) << 2;
            float4 f = *(const float4*)(A + (long)(m0 + row) * lda + k0 + c4);
            As[row][c4 + 0] = to_tf32(f.x);
            As[row][c4 + 1] = to_tf32(f.y);
            As[row][c4 + 2] = to_tf32(f.z);
            As[row][c4 + 3] = to_tf32(f.w);
        }
        if (B_KMAJOR) {
            #pragma unroll
            for (int s = 0; s < 2; ++s) {  // B tile [n][k] 128x16
                int v = t + s * 256;
                int row = v >> 2, c4 = (v & 3) << 2;
                float4 f = *(const float4*)(Bm + (long)(n0 + row) * ldb + k0 + c4);
                Bs[row][c4 + 0] = to_tf32(f.x);
                Bs[row][c4 + 1] = to_tf32(f.y);
                Bs[row][c4 + 2] = to_tf32(f.z);
                Bs[row][c4 + 3] = to_tf32(f.w);
            }
        } else {
            #pragma unroll
            for (int s = 0; s < 2; ++s) {  // B tile [k][n] 16x128 -> transpose into Bs[n][k]
                int v = t + s * 256;
                int row = v >> 5, c4 = (v & 31) << 2;
                float4 f = *(const float4*)(Bm + (long)(k0 + row) * ldb + n0 + c4);
                Bs[c4 + 0][row] = to_tf32(f.x);
                Bs[c4 + 1][row] = to_tf32(f.y);
                Bs[c4 + 2][row] = to_tf32(f.z);
                Bs[c4 + 3][row] = to_tf32(f.w);
            }
        }
        __syncthreads();

        #pragma unroll
        for (int kk = 0; kk < 16; kk += 8) {
            uint32_t a[4][4], b[4][2];
            #pragma unroll
            for (int mi = 0; mi < 4; mi++) {
                int r = wm * 64 + mi * 16 + g;
                a[mi][0] = __float_as_uint(As[r][kk + tg]);
                a[mi][1] = __float_as_uint(As[r + 8][kk + tg]);
                a[mi][2] = __float_as_uint(As[r][kk + 4 + tg]);
                a[mi][3] = __float_as_uint(As[r + 8][kk + 4 + tg]);
            }
            #pragma unroll
            for (int ni = 0; ni < 4; ni++) {
                int c = wn * 32 + ni * 8 + g;
                b[ni][0] = __float_as_uint(Bs[c][kk + tg]);
                b[ni][1] = __float_as_uint(Bs[c][kk + 4 + tg]);
            }
            #pragma unroll
            for (int mi = 0; mi < 4; mi++)
                #pragma unroll
                for (int ni = 0; ni < 4; ni++)
                    asm volatile(
                        "mma.sync.aligned.m16n8k8.row.col.f32.tf32.tf32.f32 "
                        "{%0,%1,%2,%3}, {%4,%5,%6,%7}, {%8,%9}, {%0,%1,%2,%3};\n"
                        : "+f"(acc[mi][ni][0]), "+f"(acc[mi][ni][1]),
                          "+f"(acc[mi][ni][2]), "+f"(acc[mi][ni][3])
                        : "r"(a[mi][0]), "r"(a[mi][1]), "r"(a[mi][2]), "r"(a[mi][3]),
                          "r"(b[ni][0]), "r"(b[ni][1]));
        }
        __syncthreads();
    }

    // epilogue
    #pragma unroll
    for (int mi = 0; mi < 4; mi++) {
        int r0 = m0 + wm * 64 + mi * 16 + g;
        #pragma unroll
        for (int ni = 0; ni < 4; ni++) {
            int c0 = n0 + wn * 32 + ni * 8 + 2 * tg;
            #pragma unroll
            for (int h = 0; h < 2; h++) {
                int rr = r0 + h * 8;
                #pragma unroll
                for (int w2 = 0; w2 < 2; w2++) {
                    int cc = c0 + w2;
                    float x = acc[mi][ni][h * 2 + w2];
                    if (MODE == 1) x += g_bias[cc];
                    if (MODE == 2) x = (cc <= rr - 4) ? x * scale : -65000.f;
                    C[(long)rr * ldc + cc] = x;
                }
            }
        }
    }
}

// ---------------------------------------------------------------------------
// Row softmax over g_scores + combine with decay: s <- 0.7*decay + 0.3*softmax(s)
// one block per row (16 KB row cached in smem)
// ---------------------------------------------------------------------------
__global__ __launch_bounds__(256) void softmax_combine(const float* __restrict__ decay) {
    const long row = blockIdx.x;
    float* __restrict__ srow = g_scores + row * TT;
    const float* __restrict__ drow = decay + row * TT;
    __shared__ float sh[TT];
    __shared__ float red[8];
    const int t = threadIdx.x;

    float mx = -3.4e38f;
    for (int j = t; j < TT; j += 256) {
        float v = srow[j];
        sh[j] = v;
        mx = fmaxf(mx, v);
    }
    #pragma unroll
    for (int o = 16; o; o >>= 1) mx = fmaxf(mx, __shfl_xor_sync(0xffffffffu, mx, o));
    if ((t & 31) == 0) red[t >> 5] = mx;
    __syncthreads();
    mx = red[0];
    #pragma unroll
    for (int i = 1; i < 8; i++) mx = fmaxf(mx, red[i]);

    float sum = 0.f;
    for (int j = t; j < TT; j += 256) {
        float e = expf(sh[j] - mx);
        sh[j] = e;
        sum += e;
    }
    #pragma unroll
    for (int o = 16; o; o >>= 1) sum += __shfl_xor_sync(0xffffffffu, sum, o);
    __syncthreads();  // everyone done reading red[] for max
    if ((t & 31) == 0) red[t >> 5] = sum;
    __syncthreads();
    sum = red[0];
    #pragma unroll
    for (int i = 1; i < 8; i++) sum += red[i];

    const float inv = 0.3f / sum;
    for (int j = t; j < TT; j += 256) srow[j] = fmaf(0.7f, drow[j], sh[j] * inv);
}

// ---------------------------------------------------------------------------
extern "C" void kernel_launch(void* const* d_in, const int* in_sizes, int n_in,
                              void* d_out, int out_size) {
    const float* hdc   = (const float*)d_in[0];  // [B,T,D]
    const float* decay = (const float*)d_in[1];  // [B,T,T]
    const float* Wq    = (const float*)d_in[2];  // [BOT,D]
    const float* bq    = (const float*)d_in[3];  // [BOT]
    const float* Wk    = (const float*)d_in[4];  // [BOT,D]
    const float* bk    = (const float*)d_in[5];  // [BOT]
    float* out = (float*)d_out;

    float *qk, *scores, *wptr;
    cudaGetSymbolAddress((void**)&qk, g_qk);
    cudaGetSymbolAddress((void**)&scores, g_scores);
    cudaGetSymbolAddress((void**)&wptr, g_w);

    pack_w<<<512, 256>>>(Wq, Wk, bq, bk);

    // K1: [16384,512] = hdc @ [Wq;Wk]^T + bias   (NT)
    {
        dim3 grid(512 / 128, (BB * TT) / 128, 1);
        gemm_tf32<1, true><<<grid, 256>>>(hdc, wptr, qk,
                                          BB * TT, 2 * BOT, DD, DD, DD, 2 * BOT,
                                          0, 0, 0, 1.f);
    }
    // K2: scores = q @ k^T * 1/16, masked   (NT, per batch)
    {
        dim3 grid(TT / 128, TT / 128, BB);
        gemm_tf32<2, true><<<grid, 256>>>(qk, qk + BOT, scores,
                                          TT, TT, BOT, 2 * BOT, 2 * BOT, TT,
                                          (long)TT * 2 * BOT, (long)TT * 2 * BOT,
                                          (long)TT * TT, 0.0625f);
    }
    // K3: softmax + 0.7*decay + 0.3*P (in place on g_scores)
    softmax_combine<<<BB * TT, 256>>>(decay);

    // K4: out = comb @ hdc   (NN, per batch)
    {
        dim3 grid(DD / 128, TT / 128, BB);
        gemm_tf32<0, false><<<grid, 256>>>(scores, hdc, out,
                                           TT, DD, TT, TT, DD, DD,
                                           (long)TT * TT, (long)TT * DD,
                                           (long)TT * DD, 1.f);
    }
}

// round 6
// speedup vs baseline: 2.0056x; 2.0056x over previous
#include <cuda_runtime.h>
#include <cstdint>

#define BB 4
#define TT 4096
#define DD 2048
#define BOT 256

// ------------------------- scratch (device globals) -------------------------
__device__ float g_scores[(size_t)BB * TT * TT];   // 256 MB scores -> combined (tf32)
__device__ float g_hdcT[(size_t)BB * DD * TT];     // 128 MB hdc^T (tf32)
__device__ float g_hdc32[(size_t)BB * TT * DD];    // 128 MB hdc rounded (tf32)
__device__ float g_qk[(size_t)BB * TT * 2 * BOT];  // 32 MB  q | k (tf32)
__device__ float g_w[2 * BOT * DD];                // 4 MB   packed [Wq;Wk] (tf32)
__device__ float g_bias[2 * BOT];

__device__ __forceinline__ float to_tf32(float x) {
    uint32_t u;
    asm("cvt.rna.tf32.f32 %0, %1;" : "=r"(u) : "f"(x));
    return __uint_as_float(u);
}
__device__ __forceinline__ uint32_t smem_u32(const void* p) {
    uint32_t a;
    asm("{ .reg .u64 t; cvta.to.shared.u64 t, %1; cvt.u32.u64 %0, t; }" : "=r"(a) : "l"(p));
    return a;
}
__device__ __forceinline__ void cpa16(uint32_t dst, const void* src) {
    asm volatile("cp.async.cg.shared.global [%0], [%1], 16;" :: "r"(dst), "l"(src));
}

// ------------------------------- small kernels ------------------------------
__global__ void pack_w(const float* __restrict__ Wq, const float* __restrict__ Wk,
                       const float* __restrict__ bq, const float* __restrict__ bk) {
    for (int i = blockIdx.x * blockDim.x + threadIdx.x; i < 2 * BOT * DD;
         i += gridDim.x * blockDim.x) {
        int n = i / DD, k = i - n * DD;
        g_w[i] = to_tf32((n < BOT) ? Wq[n * DD + k] : Wk[(n - BOT) * DD + k]);
    }
    int j = blockIdx.x * blockDim.x + threadIdx.x;
    if (j < 2 * BOT) g_bias[j] = (j < BOT) ? bq[j] : bk[j - BOT];
}

// transpose + round: writes g_hdcT (D-major) and g_hdc32 (rounded copy)
__global__ __launch_bounds__(256) void transpose_cvt(const float* __restrict__ hdc) {
    __shared__ float tile[32][33];
    const int b = blockIdx.z;
    const int t0 = blockIdx.x * 32, d0 = blockIdx.y * 32;
    const float* src = hdc + (long)b * TT * DD;
    float* dstT = g_hdcT + (long)b * DD * TT;
    float* dstC = g_hdc32 + (long)b * TT * DD;
    const int x = threadIdx.x, y = threadIdx.y;  // (32,8)
    #pragma unroll
    for (int s = 0; s < 32; s += 8) {
        float v = to_tf32(src[(long)(t0 + y + s) * DD + d0 + x]);
        tile[y + s][x] = v;
        dstC[(long)(t0 + y + s) * DD + d0 + x] = v;
    }
    __syncthreads();
    #pragma unroll
    for (int s = 0; s < 32; s += 8)
        dstT[(long)(d0 + y + s) * TT + t0 + x] = tile[x][y + s];
}

// --------------------- pipelined TF32 mma.sync GEMM ------------------------
// C[M,N] = A[M,K] @ B[N,K]^T, both K-major, all operands pre-rounded to tf32.
// Tile 128(M) x 256(N) x 32(K), 512 threads, 3-stage cp.async pipeline.
// MODE 0: plain; 1: +bias, tf32-round (q/k); 2: mask(j<=i-4)*scale, skip dead
#define Bb_M 128
#define Bb_N 256
#define Bb_K 32
#define NTH 512
#define STG 3
#define A_STAGE (Bb_M * Bb_K)              // 4096 floats
#define B_STAGE (Bb_N * Bb_K)              // 8192 floats
#define SMEM_FLOATS (STG * (A_STAGE + B_STAGE))
#define SMEM_BYTES (SMEM_FLOATS * 4)       // 147456

__device__ __forceinline__ float ldsw(const float* buf, int row, int col) {
    return buf[row * 32 + ((((col >> 2) ^ (row & 7)) << 2) | (col & 3))];
}

template <int MODE>
__global__ __launch_bounds__(NTH, 1) void gemm_mma(
    const float* __restrict__ A, const float* __restrict__ Bm, float* __restrict__ C,
    int K, int lda, int ldb, int ldc, long sA, long sB, long sC, float scale) {
    const int m0 = blockIdx.y * Bb_M;
    const int n0 = blockIdx.x * Bb_N;
    if (MODE == 2 && n0 > m0 + 123) return;  // fully masked: never read downstream

    A += (long)blockIdx.z * sA + (long)m0 * lda;
    Bm += (long)blockIdx.z * sB + (long)n0 * ldb;
    C += (long)blockIdx.z * sC;

    extern __shared__ float smem[];
    float* sA_ = smem;                       // [STG][A_STAGE]
    float* sB_ = smem + STG * A_STAGE;       // [STG][B_STAGE]
    const uint32_t sbA = smem_u32(sA_);
    const uint32_t sbB = smem_u32(sB_);

    const int t = threadIdx.x;
    const int warp = t >> 5, lane = t & 31;
    const int wm = warp >> 3, wn = warp & 7;  // 2 x 8 warps -> 64x32 each
    const int g = lane >> 2, tg = lane & 3;

    const int NC = K >> 5;

    // async load of one k-chunk into stage s
    auto load_stage = [&](int s, int kc) {
        const int k0 = kc << 5;
        const uint32_t ab = sbA + s * (A_STAGE * 4);
        const uint32_t bb = sbB + s * (B_STAGE * 4);
        #pragma unroll
        for (int q = 0; q < 2; ++q) {  // A: 1024 chunks of 16B
            int u = t + q * NTH, row = u >> 3, cc = u & 7;
            cpa16(ab + row * 128 + ((cc ^ (row & 7)) << 4),
                  A + (long)row * lda + k0 + cc * 4);
        }
        #pragma unroll
        for (int q = 0; q < 4; ++q) {  // B: 2048 chunks of 16B
            int u = t + q * NTH, row = u >> 3, cc = u & 7;
            cpa16(bb + row * 128 + ((cc ^ (row & 7)) << 4),
                  Bm + (long)row * ldb + k0 + cc * 4);
        }
        asm volatile("cp.async.commit_group;" ::: "memory");
    };

    float acc[4][4][4];
    #pragma unroll
    for (int i = 0; i < 4; i++)
        #pragma unroll
        for (int j = 0; j < 4; j++)
            #pragma unroll
            for (int r = 0; r < 4; r++) acc[i][j][r] = 0.f;

    load_stage(0, 0);
    load_stage(1, 1);
    load_stage(2, 2);

    for (int c = 0; c < NC; ++c) {
        const int rem = NC - 1 - c;
        if (rem >= 2) asm volatile("cp.async.wait_group 2;" ::: "memory");
        else if (rem == 1) asm volatile("cp.async.wait_group 1;" ::: "memory");
        else asm volatile("cp.async.wait_group 0;" ::: "memory");
        __syncthreads();

        const int s = c % STG;
        const float* Ab = sA_ + s * A_STAGE;
        const float* Bb = sB_ + s * B_STAGE;
        #pragma unroll
        for (int kk = 0; kk < 32; kk += 8) {
            uint32_t a[4][4], b[4][2];
            #pragma unroll
            for (int mi = 0; mi < 4; mi++) {
                int r = wm * 64 + mi * 16 + g;
                a[mi][0] = __float_as_uint(ldsw(Ab, r, kk + tg));
                a[mi][1] = __float_as_uint(ldsw(Ab, r + 8, kk + tg));
                a[mi][2] = __float_as_uint(ldsw(Ab, r, kk + 4 + tg));
                a[mi][3] = __float_as_uint(ldsw(Ab, r + 8, kk + 4 + tg));
            }
            #pragma unroll
            for (int ni = 0; ni < 4; ni++) {
                int cc = wn * 32 + ni * 8 + g;
                b[ni][0] = __float_as_uint(ldsw(Bb, cc, kk + tg));
                b[ni][1] = __float_as_uint(ldsw(Bb, cc, kk + 4 + tg));
            }
            #pragma unroll
            for (int mi = 0; mi < 4; mi++)
                #pragma unroll
                for (int ni = 0; ni < 4; ni++)
                    asm volatile(
                        "mma.sync.aligned.m16n8k8.row.col.f32.tf32.tf32.f32 "
                        "{%0,%1,%2,%3}, {%4,%5,%6,%7}, {%8,%9}, {%0,%1,%2,%3};\n"
                        : "+f"(acc[mi][ni][0]), "+f"(acc[mi][ni][1]),
                          "+f"(acc[mi][ni][2]), "+f"(acc[mi][ni][3])
                        : "r"(a[mi][0]), "r"(a[mi][1]), "r"(a[mi][2]), "r"(a[mi][3]),
                          "r"(b[ni][0]), "r"(b[ni][1]));
        }
        __syncthreads();
        if (c + 3 < NC) load_stage(s, c + 3);
    }

    // epilogue: float2 stores
    #pragma unroll
    for (int mi = 0; mi < 4; mi++) {
        const long r0 = m0 + wm * 64 + mi * 16 + g;
        #pragma unroll
        for (int ni = 0; ni < 4; ni++) {
            const int cc = n0 + wn * 32 + ni * 8 + 2 * tg;
            float b0 = 0.f, b1 = 0.f;
            if (MODE == 1) {
                b0 = __ldg(&g_bias[cc + 0]);
                b1 = __ldg(&g_bias[cc + 1]);
            }
            #pragma unroll
            for (int h = 0; h < 2; h++) {
                const long rr = r0 + h * 8;
                float x0 = acc[mi][ni][h * 2 + 0];
                float x1 = acc[mi][ni][h * 2 + 1];
                if (MODE == 1) {
                    x0 = to_tf32(x0 + b0);
                    x1 = to_tf32(x1 + b1);
                }
                if (MODE == 2) {
                    const long lim = rr - 4;
                    x0 = (cc + 0 <= lim) ? x0 * scale : -65000.f;
                    x1 = (cc + 1 <= lim) ? x1 * scale : -65000.f;
                }
                float2 v;
                v.x = x0;
                v.y = x1;
                *(float2*)(C + rr * ldc + cc) = v;
            }
        }
    }
}

// -------------------- masked softmax + decay combine -----------------------
// row i: allowed j in [0, i-4]; masked probs are exactly 0 in fp32.
// rows i<4: uniform 1/T. Output rounded to tf32 (feeds K4).
__global__ __launch_bounds__(256) void softmax_combine(const float* __restrict__ decay) {
    const long row = blockIdx.x;
    const int i = (int)(row & (TT - 1));
    float* __restrict__ srow = g_scores + row * TT;
    const float* __restrict__ drow = decay + row * TT;
    const int t = threadIdx.x;
    const int L = (i >= 4) ? (i - 3) : 0;

    if (L == 0) {
        const float u = 0.3f / TT;
        for (int j = t; j < TT; j += 256) srow[j] = to_tf32(fmaf(0.7f, drow[j], u));
        return;
    }

    __shared__ float sh[TT];
    __shared__ float red[8];
    float mx = -3.4e38f;
    for (int j = t; j < L; j += 256) {
        float v = srow[j];
        sh[j] = v;
        mx = fmaxf(mx, v);
    }
    #pragma unroll
    for (int o = 16; o; o >>= 1) mx = fmaxf(mx, __shfl_xor_sync(0xffffffffu, mx, o));
    if ((t & 31) == 0) red[t >> 5] = mx;
    __syncthreads();
    mx = red[0];
    #pragma unroll
    for (int k = 1; k < 8; k++) mx = fmaxf(mx, red[k]);

    float sum = 0.f;
    for (int j = t; j < L; j += 256) {
        float e = __expf(sh[j] - mx);
        sh[j] = e;
        sum += e;
    }
    #pragma unroll
    for (int o = 16; o; o >>= 1) sum += __shfl_xor_sync(0xffffffffu, sum, o);
    __syncthreads();
    if ((t & 31) == 0) red[t >> 5] = sum;
    __syncthreads();
    sum = red[0];
    #pragma unroll
    for (int k = 1; k < 8; k++) sum += red[k];

    const float inv = 0.3f / sum;
    for (int j = t; j < L; j += 256) srow[j] = to_tf32(fmaf(0.7f, drow[j], sh[j] * inv));
    for (int j = L + t; j < TT; j += 256) srow[j] = to_tf32(0.7f * drow[j]);
}

// --------------------------------- launch ----------------------------------
extern "C" void kernel_launch(void* const* d_in, const int* in_sizes, int n_in,
                              void* d_out, int out_size) {
    const float* hdc   = (const float*)d_in[0];
    const float* decay = (const float*)d_in[1];
    const float* Wq    = (const float*)d_in[2];
    const float* bq    = (const float*)d_in[3];
    const float* Wk    = (const float*)d_in[4];
    const float* bk    = (const float*)d_in[5];
    float* out = (float*)d_out;

    float *qk, *scores, *wptr, *hdcT, *hdc32;
    cudaGetSymbolAddress((void**)&qk, g_qk);
    cudaGetSymbolAddress((void**)&scores, g_scores);
    cudaGetSymbolAddress((void**)&wptr, g_w);
    cudaGetSymbolAddress((void**)&hdcT, g_hdcT);
    cudaGetSymbolAddress((void**)&hdc32, g_hdc32);

    cudaFuncSetAttribute(gemm_mma<0>, cudaFuncAttributeMaxDynamicSharedMemorySize, SMEM_BYTES);
    cudaFuncSetAttribute(gemm_mma<1>, cudaFuncAttributeMaxDynamicSharedMemorySize, SMEM_BYTES);
    cudaFuncSetAttribute(gemm_mma<2>, cudaFuncAttributeMaxDynamicSharedMemorySize, SMEM_BYTES);

    pack_w<<<512, 256>>>(Wq, Wk, bq, bk);
    transpose_cvt<<<dim3(TT / 32, DD / 32, BB), dim3(32, 8)>>>(hdc);

    // K1: qk[16384,512] = hdc32 @ [Wq;Wk]^T + bias
    gemm_mma<1><<<dim3(512 / Bb_N, (BB * TT) / Bb_M, 1), NTH, SMEM_BYTES>>>(
        hdc32, wptr, qk, DD, DD, DD, 2 * BOT, 0, 0, 0, 1.f);

    // K2: scores = mask(q @ k^T) / 16  (dead tiles skipped)
    gemm_mma<2><<<dim3(TT / Bb_N, TT / Bb_M, BB), NTH, SMEM_BYTES>>>(
        qk, qk + BOT, scores, BOT, 2 * BOT, 2 * BOT, TT,
        (long)TT * 2 * BOT, (long)TT * 2 * BOT, (long)TT * TT, 0.0625f);

    // K3: combined = 0.7*decay + 0.3*softmax  (in place)
    softmax_combine<<<BB * TT, 256>>>(decay);

    // K4: out = combined @ hdc  (B = hdcT, K-major)
    gemm_mma<0><<<dim3(DD / Bb_N, TT / Bb_M, BB), NTH, SMEM_BYTES>>>(
        scores, hdcT, out, TT, TT, TT, DD,
        (long)TT * TT, (long)DD * TT, (long)TT * DD, 1.f);
}

// round 7
// speedup vs baseline: 2.6766x; 1.3346x over previous
#include <cuda_runtime.h>
#include <cstdint>

#define BB 4
#define TT 4096
#define DD 2048
#define BOT 256

// ------------------------- scratch (device globals) -------------------------
__device__ float g_scores[(size_t)BB * TT * TT];   // 256 MB scores -> combined (tf32)
__device__ float g_hdcT[(size_t)BB * DD * TT];     // 128 MB hdc^T (tf32)
__device__ float g_qk[(size_t)BB * TT * 2 * BOT];  // 32 MB  q | k (tf32)
__device__ float g_w[2 * BOT * DD];                // 4 MB   packed [Wq;Wk] (tf32)
__device__ float g_bias[2 * BOT];

__device__ __forceinline__ float to_tf32(float x) {
    uint32_t u;
    asm("cvt.rna.tf32.f32 %0, %1;" : "=r"(u) : "f"(x));
    return __uint_as_float(u);
}
__device__ __forceinline__ uint32_t tf32u(uint32_t x) {
    uint32_t u;
    asm("cvt.rna.tf32.f32 %0, %1;" : "=r"(u) : "f"(__uint_as_float(x)));
    return u;
}
__device__ __forceinline__ uint32_t smem_u32(const void* p) {
    uint32_t a;
    asm("{ .reg .u64 t; cvta.to.shared.u64 t, %1; cvt.u32.u64 %0, t; }" : "=r"(a) : "l"(p));
    return a;
}
__device__ __forceinline__ void cpa16(uint32_t dst, const void* src) {
    asm volatile("cp.async.cg.shared.global [%0], [%1], 16;" :: "r"(dst), "l"(src));
}
__device__ __forceinline__ void ldmx4(uint32_t* d, uint32_t addr) {
    asm volatile("ldmatrix.sync.aligned.m8n8.x4.shared.b16 {%0,%1,%2,%3}, [%4];"
                 : "=r"(d[0]), "=r"(d[1]), "=r"(d[2]), "=r"(d[3]) : "r"(addr));
}

// ------------------------------- small kernels ------------------------------
__global__ void pack_w(const float* __restrict__ Wq, const float* __restrict__ Wk,
                       const float* __restrict__ bq, const float* __restrict__ bk) {
    for (int i = blockIdx.x * blockDim.x + threadIdx.x; i < 2 * BOT * DD;
         i += gridDim.x * blockDim.x) {
        int n = i / DD, k = i - n * DD;
        g_w[i] = to_tf32((n < BOT) ? Wq[n * DD + k] : Wk[(n - BOT) * DD + k]);
    }
    int j = blockIdx.x * blockDim.x + threadIdx.x;
    if (j < 2 * BOT) g_bias[j] = (j < BOT) ? bq[j] : bk[j - BOT];
}

// transpose + round: writes g_hdcT (D-major, tf32)
__global__ __launch_bounds__(256) void transpose_cvt(const float* __restrict__ hdc) {
    __shared__ float tile[32][33];
    const int b = blockIdx.z;
    const int t0 = blockIdx.x * 32, d0 = blockIdx.y * 32;
    const float* src = hdc + (long)b * TT * DD;
    float* dstT = g_hdcT + (long)b * DD * TT;
    const int x = threadIdx.x, y = threadIdx.y;  // (32,8)
    #pragma unroll
    for (int s = 0; s < 32; s += 8)
        tile[y + s][x] = to_tf32(src[(long)(t0 + y + s) * DD + d0 + x]);
    __syncthreads();
    #pragma unroll
    for (int s = 0; s < 32; s += 8)
        dstT[(long)(d0 + y + s) * TT + t0 + x] = tile[x][y + s];
}

// --------------------- pipelined TF32 mma.sync GEMM ------------------------
// C[M,N] = A[M,K] @ B[N,K]^T, both K-major. ldmatrix fragment loads.
// Tile 128(M) x 256(N) x 32(K), 512 threads, 3-stage cp.async, 1 sync/chunk.
// MODE 0: plain; 1: +bias, tf32-round (q/k); 2: mask(j<=i-4)*scale, skip dead
// CVTA: round A-fragments to tf32 in registers (A not pre-rounded)
#define Bb_M 128
#define Bb_N 256
#define Bb_K 32
#define NTH 512
#define STG 3
#define A_STAGE (Bb_M * Bb_K)
#define B_STAGE (Bb_N * Bb_K)
#define SMEM_BYTES (STG * (A_STAGE + B_STAGE) * 4)  // 147456

template <int MODE, bool CVTA>
__global__ __launch_bounds__(NTH, 1) void gemm_mma(
    const float* __restrict__ A, const float* __restrict__ Bm, float* __restrict__ C,
    int K, int lda, int ldb, int ldc, long sA, long sB, long sC, float scale) {
    const int m0 = blockIdx.y * Bb_M;
    const int n0 = blockIdx.x * Bb_N;
    if (MODE == 2 && n0 > m0 + 123) return;  // fully masked: never read downstream

    A += (long)blockIdx.z * sA + (long)m0 * lda;
    Bm += (long)blockIdx.z * sB + (long)n0 * ldb;
    C += (long)blockIdx.z * sC;

    extern __shared__ float smem[];
    const uint32_t sbA = smem_u32(smem);
    const uint32_t sbB = sbA + STG * A_STAGE * 4;

    const int t = threadIdx.x;
    const int warp = t >> 5, lane = t & 31;
    const int wm = warp >> 3, wn = warp & 7;  // 2 x 8 warps -> 64x32 each
    const int g = lane >> 2, tg = lane & 3;

    // ldmatrix address precompute (swizzle: chunk c of row r at (c^(r&7))<<4)
    uint32_t arow[4], axor[4];
    #pragma unroll
    for (int mi = 0; mi < 4; mi++) {
        int row = wm * 64 + mi * 16 + (lane & 15);
        arow[mi] = row * 128;
        axor[mi] = (((lane >> 4) << 4) ^ ((row & 7) << 4));
    }
    uint32_t brow[2], bxor[2];
    #pragma unroll
    for (int np = 0; np < 2; np++) {
        int row = wn * 32 + np * 16 + ((lane >> 4) << 3) + (lane & 7);
        brow[np] = row * 128;
        bxor[np] = ((((lane >> 3) & 1) << 4) ^ ((row & 7) << 4));
    }

    const int NC = K >> 5;

    auto load_stage = [&](int s, int kc) {
        const int k0 = kc << 5;
        const uint32_t ab = sbA + s * (A_STAGE * 4);
        const uint32_t bb = sbB + s * (B_STAGE * 4);
        #pragma unroll
        for (int q = 0; q < 2; ++q) {
            int u = t + q * NTH, row = u >> 3, cc = u & 7;
            cpa16(ab + row * 128 + ((cc ^ (row & 7)) << 4),
                  A + (long)row * lda + k0 + cc * 4);
        }
        #pragma unroll
        for (int q = 0; q < 4; ++q) {
            int u = t + q * NTH, row = u >> 3, cc = u & 7;
            cpa16(bb + row * 128 + ((cc ^ (row & 7)) << 4),
                  Bm + (long)row * ldb + k0 + cc * 4);
        }
        asm volatile("cp.async.commit_group;" ::: "memory");
    };

    float acc[4][4][4];
    #pragma unroll
    for (int i = 0; i < 4; i++)
        #pragma unroll
        for (int j = 0; j < 4; j++)
            #pragma unroll
            for (int r = 0; r < 4; r++) acc[i][j][r] = 0.f;

    load_stage(0, 0);
    load_stage(1, 1);

    for (int c = 0; c < NC; ++c) {
        if (c + 1 < NC) asm volatile("cp.async.wait_group 1;" ::: "memory");
        else asm volatile("cp.async.wait_group 0;" ::: "memory");
        __syncthreads();
        if (c + 2 < NC) load_stage((c + 2) % STG, c + 2);

        const int s = c % STG;
        const uint32_t Ab = sbA + s * (A_STAGE * 4);
        const uint32_t Bb = sbB + s * (B_STAGE * 4);
        #pragma unroll
        for (int ks = 0; ks < 4; ++ks) {  // k-step of 8; chunk-offset bytes = ks*32
            const uint32_t koff = ks << 5;
            uint32_t a[4][4], b[2][4];
            #pragma unroll
            for (int mi = 0; mi < 4; mi++)
                ldmx4(a[mi], Ab + arow[mi] + (koff ^ axor[mi]));
            #pragma unroll
            for (int np = 0; np < 2; np++)
                ldmx4(b[np], Bb + brow[np] + (koff ^ bxor[np]));
            if (CVTA) {
                #pragma unroll
                for (int mi = 0; mi < 4; mi++)
                    #pragma unroll
                    for (int q = 0; q < 4; q++) a[mi][q] = tf32u(a[mi][q]);
            }
            #pragma unroll
            for (int mi = 0; mi < 4; mi++)
                #pragma unroll
                for (int ni = 0; ni < 4; ni++)
                    asm volatile(
                        "mma.sync.aligned.m16n8k8.row.col.f32.tf32.tf32.f32 "
                        "{%0,%1,%2,%3}, {%4,%5,%6,%7}, {%8,%9}, {%0,%1,%2,%3};\n"
                        : "+f"(acc[mi][ni][0]), "+f"(acc[mi][ni][1]),
                          "+f"(acc[mi][ni][2]), "+f"(acc[mi][ni][3])
                        : "r"(a[mi][0]), "r"(a[mi][1]), "r"(a[mi][2]), "r"(a[mi][3]),
                          "r"(b[ni >> 1][(ni & 1) * 2]), "r"(b[ni >> 1][(ni & 1) * 2 + 1]));
        }
    }

    // epilogue: float2 stores
    #pragma unroll
    for (int mi = 0; mi < 4; mi++) {
        const long r0 = m0 + wm * 64 + mi * 16 + g;
        #pragma unroll
        for (int ni = 0; ni < 4; ni++) {
            const int cc = n0 + wn * 32 + ni * 8 + 2 * tg;
            float b0 = 0.f, b1 = 0.f;
            if (MODE == 1) {
                b0 = __ldg(&g_bias[cc + 0]);
                b1 = __ldg(&g_bias[cc + 1]);
            }
            #pragma unroll
            for (int h = 0; h < 2; h++) {
                const long rr = r0 + h * 8;
                float x0 = acc[mi][ni][h * 2 + 0];
                float x1 = acc[mi][ni][h * 2 + 1];
                if (MODE == 1) {
                    x0 = to_tf32(x0 + b0);
                    x1 = to_tf32(x1 + b1);
                }
                if (MODE == 2) {
                    const long lim = rr - 4;
                    x0 = (cc + 0 <= lim) ? x0 * scale : -65000.f;
                    x1 = (cc + 1 <= lim) ? x1 * scale : -65000.f;
                }
                float2 v;
                v.x = x0;
                v.y = x1;
                *(float2*)(C + rr * ldc + cc) = v;
            }
        }
    }
}

// -------------------- masked softmax + decay combine -----------------------
// row i: allowed j in [0, i-4]; masked probs exactly 0 in fp32.
// rows i<4: uniform 1/T. Output rounded to tf32 (feeds K4).
__global__ __launch_bounds__(256) void softmax_combine(const float* __restrict__ decay) {
    const long row = blockIdx.x;
    const int i = (int)(row & (TT - 1));
    float* __restrict__ srow = g_scores + row * TT;
    const float* __restrict__ drow = decay + row * TT;
    const int t = threadIdx.x;
    const int L = (i >= 4) ? (i - 3) : 0;

    if (L == 0) {
        const float u = 0.3f / TT;
        for (int v = t; v < TT / 4; v += 256) {
            float4 d = ((const float4*)drow)[v];
            float4 o;
            o.x = to_tf32(fmaf(0.7f, d.x, u));
            o.y = to_tf32(fmaf(0.7f, d.y, u));
            o.z = to_tf32(fmaf(0.7f, d.z, u));
            o.w = to_tf32(fmaf(0.7f, d.w, u));
            ((float4*)srow)[v] = o;
        }
        return;
    }

    __shared__ float sh[TT];
    __shared__ float red[8];
    const int L4 = L >> 2;

    float mx = -3.4e38f;
    for (int v = t; v < L4; v += 256) {
        float4 f = ((const float4*)srow)[v];
        ((float4*)sh)[v] = f;
        mx = fmaxf(mx, fmaxf(fmaxf(f.x, f.y), fmaxf(f.z, f.w)));
    }
    for (int j = (L4 << 2) + t; j < L; j += 256) {
        float v = srow[j];
        sh[j] = v;
        mx = fmaxf(mx, v);
    }
    #pragma unroll
    for (int o = 16; o; o >>= 1) mx = fmaxf(mx, __shfl_xor_sync(0xffffffffu, mx, o));
    if ((t & 31) == 0) red[t >> 5] = mx;
    __syncthreads();
    mx = red[0];
    #pragma unroll
    for (int k = 1; k < 8; k++) mx = fmaxf(mx, red[k]);

    float sum = 0.f;
    for (int v = t; v < L4; v += 256) {
        float4 f = ((const float4*)sh)[v];
        f.x = __expf(f.x - mx);
        f.y = __expf(f.y - mx);
        f.z = __expf(f.z - mx);
        f.w = __expf(f.w - mx);
        ((float4*)sh)[v] = f;
        sum += f.x + f.y + f.z + f.w;
    }
    for (int j = (L4 << 2) + t; j < L; j += 256) {
        float e = __expf(sh[j] - mx);
        sh[j] = e;
        sum += e;
    }
    #pragma unroll
    for (int o = 16; o; o >>= 1) sum += __shfl_xor_sync(0xffffffffu, sum, o);
    __syncthreads();
    if ((t & 31) == 0) red[t >> 5] = sum;
    __syncthreads();
    sum = red[0];
    #pragma unroll
    for (int k = 1; k < 8; k++) sum += red[k];

    const float inv = 0.3f / sum;
    for (int v = t; v < L4; v += 256) {
        float4 p = ((const float4*)sh)[v];
        float4 d = ((const float4*)drow)[v];
        float4 o;
        o.x = to_tf32(fmaf(0.7f, d.x, p.x * inv));
        o.y = to_tf32(fmaf(0.7f, d.y, p.y * inv));
        o.z = to_tf32(fmaf(0.7f, d.z, p.z * inv));
        o.w = to_tf32(fmaf(0.7f, d.w, p.w * inv));
        ((float4*)srow)[v] = o;
    }
    const int Lup = (L + 3) & ~3;
    for (int j = (L4 << 2) + t; j < L; j += 256)
        srow[j] = to_tf32(fmaf(0.7f, drow[j], sh[j] * inv));
    for (int j = L + t; j < Lup && j < TT; j += 256)
        srow[j] = to_tf32(0.7f * drow[j]);
    for (int v = (Lup >> 2) + t; v < TT / 4; v += 256) {
        float4 d = ((const float4*)drow)[v];
        float4 o;
        o.x = to_tf32(0.7f * d.x);
        o.y = to_tf32(0.7f * d.y);
        o.z = to_tf32(0.7f * d.z);
        o.w = to_tf32(0.7f * d.w);
        ((float4*)srow)[v] = o;
    }
}

// --------------------------------- launch ----------------------------------
extern "C" void kernel_launch(void* const* d_in, const int* in_sizes, int n_in,
                              void* d_out, int out_size) {
    const float* hdc   = (const float*)d_in[0];
    const float* decay = (const float*)d_in[1];
    const float* Wq    = (const float*)d_in[2];
    const float* bq    = (const float*)d_in[3];
    const float* Wk    = (const float*)d_in[4];
    const float* bk    = (const float*)d_in[5];
    float* out = (float*)d_out;

    float *qk, *scores, *wptr, *hdcT;
    cudaGetSymbolAddress((void**)&qk, g_qk);
    cudaGetSymbolAddress((void**)&scores, g_scores);
    cudaGetSymbolAddress((void**)&wptr, g_w);
    cudaGetSymbolAddress((void**)&hdcT, g_hdcT);

    cudaFuncSetAttribute(gemm_mma<0, false>, cudaFuncAttributeMaxDynamicSharedMemorySize, SMEM_BYTES);
    cudaFuncSetAttribute(gemm_mma<1, true>, cudaFuncAttributeMaxDynamicSharedMemorySize, SMEM_BYTES);
    cudaFuncSetAttribute(gemm_mma<2, false>, cudaFuncAttributeMaxDynamicSharedMemorySize, SMEM_BYTES);

    pack_w<<<512, 256>>>(Wq, Wk, bq, bk);
    transpose_cvt<<<dim3(TT / 32, DD / 32, BB), dim3(32, 8)>>>(hdc);

    // K1: qk[16384,512] = hdc @ [Wq;Wk]^T + bias  (A rounded in-register)
    gemm_mma<1, true><<<dim3(512 / Bb_N, (BB * TT) / Bb_M, 1), NTH, SMEM_BYTES>>>(
        hdc, wptr, qk, DD, DD, DD, 2 * BOT, 0, 0, 0, 1.f);

    // K2: scores = mask(q @ k^T) / 16  (dead tiles skipped)
    gemm_mma<2, false><<<dim3(TT / Bb_N, TT / Bb_M, BB), NTH, SMEM_BYTES>>>(
        qk, qk + BOT, scores, BOT, 2 * BOT, 2 * BOT, TT,
        (long)TT * 2 * BOT, (long)TT * 2 * BOT, (long)TT * TT, 0.0625f);

    // K3: combined = 0.7*decay + 0.3*softmax  (in place)
    softmax_combine<<<BB * TT, 256>>>(decay);

    // K4: out = combined @ hdc  (B = hdcT, K-major)
    gemm_mma<0, false><<<dim3(DD / Bb_N, TT / Bb_M, BB), NTH, SMEM_BYTES>>>(
        scores, hdcT, out, TT, TT, TT, DD,
        (long)TT * TT, (long)DD * TT, (long)TT * DD, 1.f);
}

// round 8
// speedup vs baseline: 2.7741x; 1.0364x over previous
#include <cuda_runtime.h>
#include <cstdint>

#define BB 4
#define TT 4096
#define DD 2048
#define BOT 256

// ------------------------- scratch (device globals) -------------------------
__device__ float g_scores[(size_t)BB * TT * TT];   // 256 MB scores -> combined (tf32)
__device__ float g_hdcT[(size_t)BB * DD * TT];     // 128 MB hdc^T (tf32)
__device__ float g_qk[(size_t)BB * TT * 2 * BOT];  // 32 MB  q | k (tf32)
__device__ float g_w[2 * BOT * DD];                // 4 MB   packed [Wq;Wk] (tf32)
__device__ float g_bias[2 * BOT];

__device__ __forceinline__ float to_tf32(float x) {
    uint32_t u;
    asm("cvt.rna.tf32.f32 %0, %1;" : "=r"(u) : "f"(x));
    return __uint_as_float(u);
}
__device__ __forceinline__ uint32_t tf32u(uint32_t x) {
    uint32_t u;
    asm("cvt.rna.tf32.f32 %0, %1;" : "=r"(u) : "f"(__uint_as_float(x)));
    return u;
}
__device__ __forceinline__ uint32_t smem_u32(const void* p) {
    uint32_t a;
    asm("{ .reg .u64 t; cvta.to.shared.u64 t, %1; cvt.u32.u64 %0, t; }" : "=r"(a) : "l"(p));
    return a;
}
__device__ __forceinline__ void cpa16(uint32_t dst, const void* src) {
    asm volatile("cp.async.cg.shared.global [%0], [%1], 16;" :: "r"(dst), "l"(src));
}
__device__ __forceinline__ void ldmx4(uint32_t* d, uint32_t addr) {
    asm volatile("ldmatrix.sync.aligned.m8n8.x4.shared.b16 {%0,%1,%2,%3}, [%4];"
                 : "=r"(d[0]), "=r"(d[1]), "=r"(d[2]), "=r"(d[3]) : "r"(addr));
}

// ------------------------------- small kernels ------------------------------
__global__ void pack_w(const float* __restrict__ Wq, const float* __restrict__ Wk,
                       const float* __restrict__ bq, const float* __restrict__ bk) {
    for (int i = blockIdx.x * blockDim.x + threadIdx.x; i < 2 * BOT * DD;
         i += gridDim.x * blockDim.x) {
        int n = i / DD, k = i - n * DD;
        g_w[i] = to_tf32((n < BOT) ? Wq[n * DD + k] : Wk[(n - BOT) * DD + k]);
    }
    int j = blockIdx.x * blockDim.x + threadIdx.x;
    if (j < 2 * BOT) g_bias[j] = (j < BOT) ? bq[j] : bk[j - BOT];
}

// transpose + round: writes g_hdcT (D-major, tf32)
__global__ __launch_bounds__(256) void transpose_cvt(const float* __restrict__ hdc) {
    __shared__ float tile[32][33];
    const int b = blockIdx.z;
    const int t0 = blockIdx.x * 32, d0 = blockIdx.y * 32;
    const float* src = hdc + (long)b * TT * DD;
    float* dstT = g_hdcT + (long)b * DD * TT;
    const int x = threadIdx.x, y = threadIdx.y;  // (32,8)
    #pragma unroll
    for (int s = 0; s < 32; s += 8)
        tile[y + s][x] = to_tf32(src[(long)(t0 + y + s) * DD + d0 + x]);
    __syncthreads();
    #pragma unroll
    for (int s = 0; s < 32; s += 8)
        dstT[(long)(d0 + y + s) * TT + t0 + x] = tile[x][y + s];
}

// --------------------- pipelined TF32 mma.sync GEMM ------------------------
// C[M,N] = A[M,K] @ B[N,K]^T, both K-major. ldmatrix fragment loads.
// Tile 128(M) x 128(N) x 32(K), 256 threads, 2 CTAs/SM, 3-stage cp.async.
// MODE 0: plain; 1: +bias, tf32-round (q/k); 2: mask(j<=i-4)*scale, skip dead
// CVTA: round A-fragments to tf32 in registers (A not pre-rounded)
#define Bb_M 128
#define Bb_N 128
#define Bb_K 32
#define NTH 256
#define STG 3
#define A_STAGE (Bb_M * Bb_K)
#define B_STAGE (Bb_N * Bb_K)
#define SMEM_BYTES (STG * (A_STAGE + B_STAGE) * 4)  // 98304

template <int MODE, bool CVTA>
__global__ __launch_bounds__(NTH, 2) void gemm_mma(
    const float* __restrict__ A, const float* __restrict__ Bm, float* __restrict__ C,
    int K, int lda, int ldb, int ldc, long sA, long sB, long sC, float scale) {
    const int m0 = blockIdx.y * Bb_M;
    const int n0 = blockIdx.x * Bb_N;
    if (MODE == 2 && n0 > m0 + 123) return;  // fully masked: never read downstream

    A += (long)blockIdx.z * sA + (long)m0 * lda;
    Bm += (long)blockIdx.z * sB + (long)n0 * ldb;
    C += (long)blockIdx.z * sC;

    extern __shared__ float smem[];
    const uint32_t sbA = smem_u32(smem);
    const uint32_t sbB = sbA + STG * A_STAGE * 4;

    const int t = threadIdx.x;
    const int warp = t >> 5, lane = t & 31;
    const int wm = warp >> 2, wn = warp & 3;  // 2 x 4 warps -> 64x32 each
    const int g = lane >> 2, tg = lane & 3;

    // ldmatrix address precompute (swizzle: chunk c of row r at (c^(r&7))<<4)
    uint32_t arow[4], axor[4];
    #pragma unroll
    for (int mi = 0; mi < 4; mi++) {
        int row = wm * 64 + mi * 16 + (lane & 15);
        arow[mi] = row * 128;
        axor[mi] = (((lane >> 4) << 4) ^ ((row & 7) << 4));
    }
    uint32_t brow[2], bxor[2];
    #pragma unroll
    for (int np = 0; np < 2; np++) {
        int row = wn * 32 + np * 16 + ((lane >> 4) << 3) + (lane & 7);
        brow[np] = row * 128;
        bxor[np] = ((((lane >> 3) & 1) << 4) ^ ((row & 7) << 4));
    }

    const int NC = K >> 5;

    auto load_stage = [&](int s, int kc) {
        const int k0 = kc << 5;
        const uint32_t ab = sbA + s * (A_STAGE * 4);
        const uint32_t bb = sbB + s * (B_STAGE * 4);
        #pragma unroll
        for (int q = 0; q < 4; ++q) {  // A: 128x32 = 1024 x 16B
            int u = t + q * NTH, row = u >> 3, cc = u & 7;
            cpa16(ab + row * 128 + ((cc ^ (row & 7)) << 4),
                  A + (long)row * lda + k0 + cc * 4);
        }
        #pragma unroll
        for (int q = 0; q < 4; ++q) {  // B: 128x32 = 1024 x 16B
            int u = t + q * NTH, row = u >> 3, cc = u & 7;
            cpa16(bb + row * 128 + ((cc ^ (row & 7)) << 4),
                  Bm + (long)row * ldb + k0 + cc * 4);
        }
        asm volatile("cp.async.commit_group;" ::: "memory");
    };

    float acc[4][4][4];
    #pragma unroll
    for (int i = 0; i < 4; i++)
        #pragma unroll
        for (int j = 0; j < 4; j++)
            #pragma unroll
            for (int r = 0; r < 4; r++) acc[i][j][r] = 0.f;

    load_stage(0, 0);
    load_stage(1, 1);

    for (int c = 0; c < NC; ++c) {
        if (c + 1 < NC) asm volatile("cp.async.wait_group 1;" ::: "memory");
        else asm volatile("cp.async.wait_group 0;" ::: "memory");
        __syncthreads();
        if (c + 2 < NC) load_stage((c + 2) % STG, c + 2);

        const int s = c % STG;
        const uint32_t Ab = sbA + s * (A_STAGE * 4);
        const uint32_t Bb = sbB + s * (B_STAGE * 4);
        #pragma unroll
        for (int ks = 0; ks < 4; ++ks) {  // k-step of 8; chunk-offset bytes = ks*32
            const uint32_t koff = ks << 5;
            uint32_t a[4][4], b[2][4];
            #pragma unroll
            for (int mi = 0; mi < 4; mi++)
                ldmx4(a[mi], Ab + arow[mi] + (koff ^ axor[mi]));
            #pragma unroll
            for (int np = 0; np < 2; np++)
                ldmx4(b[np], Bb + brow[np] + (koff ^ bxor[np]));
            if (CVTA) {
                #pragma unroll
                for (int mi = 0; mi < 4; mi++)
                    #pragma unroll
                    for (int q = 0; q < 4; q++) a[mi][q] = tf32u(a[mi][q]);
            }
            #pragma unroll
            for (int mi = 0; mi < 4; mi++)
                #pragma unroll
                for (int ni = 0; ni < 4; ni++)
                    asm volatile(
                        "mma.sync.aligned.m16n8k8.row.col.f32.tf32.tf32.f32 "
                        "{%0,%1,%2,%3}, {%4,%5,%6,%7}, {%8,%9}, {%0,%1,%2,%3};\n"
                        : "+f"(acc[mi][ni][0]), "+f"(acc[mi][ni][1]),
                          "+f"(acc[mi][ni][2]), "+f"(acc[mi][ni][3])
                        : "r"(a[mi][0]), "r"(a[mi][1]), "r"(a[mi][2]), "r"(a[mi][3]),
                          "r"(b[ni >> 1][(ni & 1) * 2]), "r"(b[ni >> 1][(ni & 1) * 2 + 1]));
        }
    }

    // epilogue: float2 stores
    #pragma unroll
    for (int mi = 0; mi < 4; mi++) {
        const long r0 = m0 + wm * 64 + mi * 16 + g;
        #pragma unroll
        for (int ni = 0; ni < 4; ni++) {
            const int cc = n0 + wn * 32 + ni * 8 + 2 * tg;
            float b0 = 0.f, b1 = 0.f;
            if (MODE == 1) {
                b0 = __ldg(&g_bias[cc + 0]);
                b1 = __ldg(&g_bias[cc + 1]);
            }
            #pragma unroll
            for (int h = 0; h < 2; h++) {
                const long rr = r0 + h * 8;
                float x0 = acc[mi][ni][h * 2 + 0];
                float x1 = acc[mi][ni][h * 2 + 1];
                if (MODE == 1) {
                    x0 = to_tf32(x0 + b0);
                    x1 = to_tf32(x1 + b1);
                }
                if (MODE == 2) {
                    const long lim = rr - 4;
                    x0 = (cc + 0 <= lim) ? x0 * scale : -65000.f;
                    x1 = (cc + 1 <= lim) ? x1 * scale : -65000.f;
                }
                float2 v;
                v.x = x0;
                v.y = x1;
                *(float2*)(C + rr * ldc + cc) = v;
            }
        }
    }
}

// -------------------- masked softmax + decay combine -----------------------
// row i: allowed j in [0, i-4]; masked probs exactly 0 in fp32.
// rows i<4: uniform 1/T. Output rounded to tf32 (feeds K4).
__global__ __launch_bounds__(256) void softmax_combine(const float* __restrict__ decay) {
    const long row = blockIdx.x;
    const int i = (int)(row & (TT - 1));
    float* __restrict__ srow = g_scores + row * TT;
    const float* __restrict__ drow = decay + row * TT;
    const int t = threadIdx.x;
    const int L = (i >= 4) ? (i - 3) : 0;

    if (L == 0) {
        const float u = 0.3f / TT;
        for (int v = t; v < TT / 4; v += 256) {
            float4 d = ((const float4*)drow)[v];
            float4 o;
            o.x = to_tf32(fmaf(0.7f, d.x, u));
            o.y = to_tf32(fmaf(0.7f, d.y, u));
            o.z = to_tf32(fmaf(0.7f, d.z, u));
            o.w = to_tf32(fmaf(0.7f, d.w, u));
            ((float4*)srow)[v] = o;
        }
        return;
    }

    __shared__ float sh[TT];
    __shared__ float red[8];
    const int L4 = L >> 2;

    float mx = -3.4e38f;
    for (int v = t; v < L4; v += 256) {
        float4 f = ((const float4*)srow)[v];
        ((float4*)sh)[v] = f;
        mx = fmaxf(mx, fmaxf(fmaxf(f.x, f.y), fmaxf(f.z, f.w)));
    }
    for (int j = (L4 << 2) + t; j < L; j += 256) {
        float v = srow[j];
        sh[j] = v;
        mx = fmaxf(mx, v);
    }
    #pragma unroll
    for (int o = 16; o; o >>= 1) mx = fmaxf(mx, __shfl_xor_sync(0xffffffffu, mx, o));
    if ((t & 31) == 0) red[t >> 5] = mx;
    __syncthreads();
    mx = red[0];
    #pragma unroll
    for (int k = 1; k < 8; k++) mx = fmaxf(mx, red[k]);

    float sum = 0.f;
    for (int v = t; v < L4; v += 256) {
        float4 f = ((const float4*)sh)[v];
        f.x = __expf(f.x - mx);
        f.y = __expf(f.y - mx);
        f.z = __expf(f.z - mx);
        f.w = __expf(f.w - mx);
        ((float4*)sh)[v] = f;
        sum += f.x + f.y + f.z + f.w;
    }
    for (int j = (L4 << 2) + t; j < L; j += 256) {
        float e = __expf(sh[j] - mx);
        sh[j] = e;
        sum += e;
    }
    #pragma unroll
    for (int o = 16; o; o >>= 1) sum += __shfl_xor_sync(0xffffffffu, sum, o);
    __syncthreads();
    if ((t & 31) == 0) red[t >> 5] = sum;
    __syncthreads();
    sum = red[0];
    #pragma unroll
    for (int k = 1; k < 8; k++) sum += red[k];

    const float inv = 0.3f / sum;
    for (int v = t; v < L4; v += 256) {
        float4 p = ((const float4*)sh)[v];
        float4 d = ((const float4*)drow)[v];
        float4 o;
        o.x = to_tf32(fmaf(0.7f, d.x, p.x * inv));
        o.y = to_tf32(fmaf(0.7f, d.y, p.y * inv));
        o.z = to_tf32(fmaf(0.7f, d.z, p.z * inv));
        o.w = to_tf32(fmaf(0.7f, d.w, p.w * inv));
        ((float4*)srow)[v] = o;
    }
    const int Lup = (L + 3) & ~3;
    for (int j = (L4 << 2) + t; j < L; j += 256)
        srow[j] = to_tf32(fmaf(0.7f, drow[j], sh[j] * inv));
    for (int j = L + t; j < Lup && j < TT; j += 256)
        srow[j] = to_tf32(0.7f * drow[j]);
    for (int v = (Lup >> 2) + t; v < TT / 4; v += 256) {
        float4 d = ((const float4*)drow)[v];
        float4 o;
        o.x = to_tf32(0.7f * d.x);
        o.y = to_tf32(0.7f * d.y);
        o.z = to_tf32(0.7f * d.z);
        o.w = to_tf32(0.7f * d.w);
        ((float4*)srow)[v] = o;
    }
}

// --------------------------------- launch ----------------------------------
extern "C" void kernel_launch(void* const* d_in, const int* in_sizes, int n_in,
                              void* d_out, int out_size) {
    const float* hdc   = (const float*)d_in[0];
    const float* decay = (const float*)d_in[1];
    const float* Wq    = (const float*)d_in[2];
    const float* bq    = (const float*)d_in[3];
    const float* Wk    = (const float*)d_in[4];
    const float* bk    = (const float*)d_in[5];
    float* out = (float*)d_out;

    float *qk, *scores, *wptr, *hdcT;
    cudaGetSymbolAddress((void**)&qk, g_qk);
    cudaGetSymbolAddress((void**)&scores, g_scores);
    cudaGetSymbolAddress((void**)&wptr, g_w);
    cudaGetSymbolAddress((void**)&hdcT, g_hdcT);

    cudaFuncSetAttribute(gemm_mma<0, false>, cudaFuncAttributeMaxDynamicSharedMemorySize, SMEM_BYTES);
    cudaFuncSetAttribute(gemm_mma<1, true>, cudaFuncAttributeMaxDynamicSharedMemorySize, SMEM_BYTES);
    cudaFuncSetAttribute(gemm_mma<2, false>, cudaFuncAttributeMaxDynamicSharedMemorySize, SMEM_BYTES);

    pack_w<<<512, 256>>>(Wq, Wk, bq, bk);
    transpose_cvt<<<dim3(TT / 32, DD / 32, BB), dim3(32, 8)>>>(hdc);

    // K1: qk[16384,512] = hdc @ [Wq;Wk]^T + bias  (A rounded in-register)
    gemm_mma<1, true><<<dim3(512 / Bb_N, (BB * TT) / Bb_M, 1), NTH, SMEM_BYTES>>>(
        hdc, wptr, qk, DD, DD, DD, 2 * BOT, 0, 0, 0, 1.f);

    // K2: scores = mask(q @ k^T) / 16  (dead tiles skipped)
    gemm_mma<2, false><<<dim3(TT / Bb_N, TT / Bb_M, BB), NTH, SMEM_BYTES>>>(
        qk, qk + BOT, scores, BOT, 2 * BOT, 2 * BOT, TT,
        (long)TT * 2 * BOT, (long)TT * 2 * BOT, (long)TT * TT, 0.0625f);

    // K3: combined = 0.7*decay + 0.3*softmax  (in place)
    softmax_combine<<<BB * TT, 256>>>(decay);

    // K4: out = combined @ hdc  (B = hdcT, K-major)
    gemm_mma<0, false><<<dim3(DD / Bb_N, TT / Bb_M, BB), NTH, SMEM_BYTES>>>(
        scores, hdcT, out, TT, TT, TT, DD,
        (long)TT * TT, (long)DD * TT, (long)TT * DD, 1.f);
}